// round 3
// baseline (speedup 1.0000x reference)
#include <cuda_runtime.h>

#define N_NODES   50000
#define N_REL     10
#define R2        21            // 2*r + 1
#define N_TRIPLES 500000
#define ETOT      (2 * N_TRIPLES + N_NODES)   // 1,050,000 augmented edges
#define BATCH     16384
#define HID       64

// Scratch (static __device__ — no allocation at runtime)
__device__ int   g_colsum[R2 * N_NODES];       // 4.2 MB
__device__ float g_h[N_NODES * HID];           // 12.8 MB
__device__ float g_nodes[N_NODES * HID];       // 12.8 MB
__device__ int   g_flag[N_NODES];              // 0.2 MB

// Augmented-edge decode: idx in [0, ETOT)
//   [0, E)        : forward   src=s, p=p,     o=o
//   [E, E+n)      : self-loop src=i, p=2r,    o=i
//   [E+n, 2E+n)   : inverse   src=o, p=p+r,   o=s
__device__ __forceinline__ void decode_edge(int idx, const int* __restrict__ triples,
                                            int& src, int& col, int& p, int& o) {
    if (idx < N_TRIPLES) {
        int s  = triples[3 * idx + 0];
        int pp = triples[3 * idx + 1];
        int oo = triples[3 * idx + 2];
        src = s; p = pp; o = oo;
    } else if (idx < N_TRIPLES + N_NODES) {
        int i = idx - N_TRIPLES;
        src = i; p = 2 * N_REL; o = i;
    } else {
        int e  = idx - N_TRIPLES - N_NODES;
        int s  = triples[3 * e + 0];
        int pp = triples[3 * e + 1];
        int oo = triples[3 * e + 2];
        src = oo; p = pp + N_REL; o = s;
    }
    col = p * N_NODES + o;
}

// ---------------------------------------------------------------------------
// K0: init scratch. h <- b0 broadcast, nodes <- b1 broadcast, colsum/flag <- 0
// ---------------------------------------------------------------------------
__global__ void k_init(const float* __restrict__ b0, const float* __restrict__ b1) {
    int idx = blockIdx.x * blockDim.x + threadIdx.x;
    if (idx < N_NODES * HID) {
        g_h[idx]     = b0[idx & 63];
        g_nodes[idx] = b1[idx & 63];
    }
    if (idx < R2 * N_NODES) g_colsum[idx] = 0;
    if (idx < N_NODES)      g_flag[idx]   = 0;
}

// ---------------------------------------------------------------------------
// K1: flag nodes that appear as subject/object in the batch (layer-2 filter)
// ---------------------------------------------------------------------------
__global__ void k_flag(const int* __restrict__ batch) {
    int b = blockIdx.x * blockDim.x + threadIdx.x;
    if (b < BATCH) {
        g_flag[batch[3 * b + 0]] = 1;
        g_flag[batch[3 * b + 2]] = 1;
    }
}

// ---------------------------------------------------------------------------
// K2: colsum[col] = number of augmented edges with that (p_all, o_all)
// ---------------------------------------------------------------------------
__global__ void k_count(const int* __restrict__ triples) {
    int idx = blockIdx.x * blockDim.x + threadIdx.x;
    if (idx >= ETOT) return;
    int src, col, p, o;
    decode_edge(idx, triples, src, col, p, o);
    atomicAdd(&g_colsum[col], 1);
}

// ---------------------------------------------------------------------------
// K3: layer 1 — h[src] += val * w0[col], 16 threads/edge, float4
// ---------------------------------------------------------------------------
__global__ void k_layer1(const int* __restrict__ triples, const float* __restrict__ w0) {
    int t    = blockIdx.x * blockDim.x + threadIdx.x;
    int e    = t >> 4;
    int lane = t & 15;
    if (e >= ETOT) return;
    int src, col, p, o;
    decode_edge(e, triples, src, col, p, o);
    float val = 1.0f / (float)g_colsum[col];

    float4 v = __ldg(reinterpret_cast<const float4*>(w0) + (size_t)col * 16 + lane);
    float* hdst = g_h + src * 64 + lane * 4;
    atomicAdd(hdst + 0, val * v.x);
    atomicAdd(hdst + 1, val * v.y);
    atomicAdd(hdst + 2, val * v.z);
    atomicAdd(hdst + 3, val * v.w);
}

// ---------------------------------------------------------------------------
// K4: layer 2 — nodes[src] += val * (h[o] @ w1[p]), only if flag[src].
// 16 threads/edge; each thread computes 4 output columns (float4 w1 loads);
// h row read as float4 (16 loads/thread instead of 64).
// ---------------------------------------------------------------------------
__global__ void k_layer2(const int* __restrict__ triples, const float* __restrict__ w1) {
    int t    = blockIdx.x * blockDim.x + threadIdx.x;
    int e    = t >> 4;
    int lane = t & 15;
    if (e >= ETOT) return;
    int src, col, p, o;
    decode_edge(e, triples, src, col, p, o);
    if (!g_flag[src]) return;                    // batch-filter: ~48% of edges survive
    float val = 1.0f / (float)g_colsum[col];

    const float4* W    = reinterpret_cast<const float4*>(w1 + p * 4096);  // 64x64
    const float4* hrow = reinterpret_cast<const float4*>(g_h + o * 64);

    float4 acc = make_float4(0.f, 0.f, 0.f, 0.f);
    #pragma unroll
    for (int i4 = 0; i4 < 16; i4++) {
        float4 hv = __ldg(hrow + i4);            // broadcast within edge group
        float4 w;
        w = __ldg(W + (i4 * 4 + 0) * 16 + lane);
        acc.x = fmaf(hv.x, w.x, acc.x); acc.y = fmaf(hv.x, w.y, acc.y);
        acc.z = fmaf(hv.x, w.z, acc.z); acc.w = fmaf(hv.x, w.w, acc.w);
        w = __ldg(W + (i4 * 4 + 1) * 16 + lane);
        acc.x = fmaf(hv.y, w.x, acc.x); acc.y = fmaf(hv.y, w.y, acc.y);
        acc.z = fmaf(hv.y, w.z, acc.z); acc.w = fmaf(hv.y, w.w, acc.w);
        w = __ldg(W + (i4 * 4 + 2) * 16 + lane);
        acc.x = fmaf(hv.z, w.x, acc.x); acc.y = fmaf(hv.z, w.y, acc.y);
        acc.z = fmaf(hv.z, w.z, acc.z); acc.w = fmaf(hv.z, w.w, acc.w);
        w = __ldg(W + (i4 * 4 + 3) * 16 + lane);
        acc.x = fmaf(hv.w, w.x, acc.x); acc.y = fmaf(hv.w, w.y, acc.y);
        acc.z = fmaf(hv.w, w.z, acc.z); acc.w = fmaf(hv.w, w.w, acc.w);
    }
    float* nd = g_nodes + src * 64 + lane * 4;
    atomicAdd(nd + 0, val * acc.x);
    atomicAdd(nd + 1, val * acc.y);
    atomicAdd(nd + 2, val * acc.z);
    atomicAdd(nd + 3, val * acc.w);
}

// ---------------------------------------------------------------------------
// K5: scores[b] = sum_j nodes[si,j] * relations[pi,j] * nodes[oi,j]
// one warp per batch element
// ---------------------------------------------------------------------------
__global__ void k_score(const int* __restrict__ batch, const float* __restrict__ rel,
                        float* __restrict__ out) {
    int t    = blockIdx.x * blockDim.x + threadIdx.x;
    int b    = t >> 5;
    int lane = t & 31;
    if (b >= BATCH) return;
    int si = batch[3 * b + 0];
    int pi = batch[3 * b + 1];
    int oi = batch[3 * b + 2];

    const float* ns = g_nodes + si * 64;
    const float* no = g_nodes + oi * 64;
    const float* rr = rel + pi * 64;
    float a = ns[lane]      * rr[lane]      * no[lane]
            + ns[lane + 32] * rr[lane + 32] * no[lane + 32];
    #pragma unroll
    for (int off = 16; off; off >>= 1)
        a += __shfl_xor_sync(0xffffffffu, a, off);
    if (lane == 0) out[b] = a;
}

// ---------------------------------------------------------------------------
extern "C" void kernel_launch(void* const* d_in, const int* in_sizes, int n_in,
                              void* d_out, int out_size) {
    const int*   batch     = (const int*)  d_in[0];   // (16384, 3)
    const int*   triples   = (const int*)  d_in[1];   // (500000, 3)
    const float* w0        = (const float*)d_in[2];   // (21, 50000, 64)
    const float* b0        = (const float*)d_in[3];   // (64,)
    const float* w1        = (const float*)d_in[4];   // (21, 64, 64)
    const float* b1        = (const float*)d_in[5];   // (64,)
    const float* relations = (const float*)d_in[6];   // (10, 64)
    float* out = (float*)d_out;                       // (16384,)

    const int TPB = 256;

    // init: covers N_NODES*HID = 3.2M elements (superset of colsum/flag ranges)
    k_init<<<(N_NODES * HID + TPB - 1) / TPB, TPB>>>(b0, b1);

    k_flag<<<(BATCH + TPB - 1) / TPB, TPB>>>(batch);

    k_count<<<(ETOT + TPB - 1) / TPB, TPB>>>(triples);

    {
        long long threads = (long long)ETOT * 16;
        k_layer1<<<(int)((threads + TPB - 1) / TPB), TPB>>>(triples, w0);
    }

    {
        long long threads = (long long)ETOT * 16;
        k_layer2<<<(int)((threads + TPB - 1) / TPB), TPB>>>(triples, w1);
    }

    {
        long long threads = (long long)BATCH * 32;
        k_score<<<(int)((threads + TPB - 1) / TPB), TPB>>>(batch, relations, out);
    }
}

// round 7
// speedup vs baseline: 1.6912x; 1.6912x over previous
#include <cuda_runtime.h>

#define N_NODES   50000
#define N_REL     10
#define R2        21
#define N_TRIPLES 500000
#define ETOT      (2 * N_TRIPLES + N_NODES)   // 1,050,000 augmented edges
#define BATCH     16384
#define HID       64
#define KEYN      (N_NODES * R2)              // 1,050,000 keys (src*21+p)
#define SCAN_CHUNK 4096
#define SCAN_NB   ((KEYN + SCAN_CHUNK - 1) / SCAN_CHUNK)   // 257

// Static scratch (no runtime allocation)
__device__ int   g_colsum[KEYN];        // histogram over col = p*N + o
__device__ int   g_keycnt[KEYN];        // histogram over key = src*R2 + p
__device__ int   g_keyoff[KEYN];        // exclusive scan of keycnt (mutated by scatter)
__device__ int   g_scanblk[512];        // scan partials
__device__ int   g_sorted[ETOT];        // packed (p<<16)|o, sorted by key
__device__ float g_h[N_NODES * HID];
__device__ float g_nodes[N_NODES * HID];
__device__ int   g_flag[N_NODES];
__device__ int   g_list[N_NODES];
__device__ int   g_cnt[1];

__device__ __forceinline__ void decode_edge(int idx, const int* __restrict__ triples,
                                            int& src, int& p, int& o) {
    if (idx < N_TRIPLES) {
        src = triples[3 * idx + 0];
        p   = triples[3 * idx + 1];
        o   = triples[3 * idx + 2];
    } else if (idx < N_TRIPLES + N_NODES) {
        int i = idx - N_TRIPLES;
        src = i; p = 2 * N_REL; o = i;
    } else {
        int e = idx - N_TRIPLES - N_NODES;
        src = triples[3 * e + 2];
        p   = triples[3 * e + 1] + N_REL;
        o   = triples[3 * e + 0];
    }
}

// ---------------------------------------------------------------------------
__global__ void k_init() {
    int idx = blockIdx.x * blockDim.x + threadIdx.x;
    if (idx < KEYN) { g_colsum[idx] = 0; g_keycnt[idx] = 0; }
    if (idx < N_NODES) g_flag[idx] = 0;
    if (idx == 0) g_cnt[0] = 0;
}

// ---------------------------------------------------------------------------
__global__ void k_hist(const int* __restrict__ triples) {
    int idx = blockIdx.x * blockDim.x + threadIdx.x;
    if (idx >= ETOT) return;
    int src, p, o;
    decode_edge(idx, triples, src, p, o);
    atomicAdd(&g_colsum[p * N_NODES + o], 1);
    atomicAdd(&g_keycnt[src * R2 + p], 1);
}

// ---------------------------------------------------------------------------
// 3-pass exclusive scan of g_keycnt -> g_keyoff
// ---------------------------------------------------------------------------
__global__ void k_scanA() {
    int b = blockIdx.x, tid = threadIdx.x;
    int base = b * SCAN_CHUNK + tid * 16;
    int s = 0;
    #pragma unroll
    for (int j = 0; j < 16; j++) {
        int idx = base + j;
        if (idx < KEYN) s += g_keycnt[idx];
    }
    __shared__ int sh[256];
    sh[tid] = s; __syncthreads();
    for (int off = 128; off; off >>= 1) {
        if (tid < off) sh[tid] += sh[tid + off];
        __syncthreads();
    }
    if (tid == 0) g_scanblk[b] = sh[0];
}

__global__ void k_scanB() {
    int tid = threadIdx.x;              // 512 threads, 1 block
    __shared__ int sh[512];
    int orig = (tid < SCAN_NB) ? g_scanblk[tid] : 0;
    sh[tid] = orig; __syncthreads();
    for (int off = 1; off < 512; off <<= 1) {
        int add = (tid >= off) ? sh[tid - off] : 0;
        __syncthreads();
        sh[tid] += add;
        __syncthreads();
    }
    if (tid < SCAN_NB) g_scanblk[tid] = sh[tid] - orig;   // exclusive
}

__global__ void k_scanC() {
    int b = blockIdx.x, tid = threadIdx.x;
    int base = b * SCAN_CHUNK + tid * 16;
    int v[16];
    #pragma unroll
    for (int j = 0; j < 16; j++) {
        int idx = base + j;
        v[j] = (idx < KEYN) ? g_keycnt[idx] : 0;
    }
    int tot = 0;
    #pragma unroll
    for (int j = 0; j < 16; j++) { int t = v[j]; v[j] = tot; tot += t; }
    __shared__ int sh[256];
    sh[tid] = tot; __syncthreads();
    int orig = tot;
    for (int off = 1; off < 256; off <<= 1) {
        int add = (tid >= off) ? sh[tid - off] : 0;
        __syncthreads();
        sh[tid] += add;
        __syncthreads();
    }
    int texcl = sh[tid] - orig + g_scanblk[b];
    #pragma unroll
    for (int j = 0; j < 16; j++) {
        int idx = base + j;
        if (idx < KEYN) g_keyoff[idx] = texcl + v[j];
    }
}

// ---------------------------------------------------------------------------
// Scatter: after this, g_keyoff[k] = exclusive END of key k (= start of k+1)
// ---------------------------------------------------------------------------
__global__ void k_scatter(const int* __restrict__ triples) {
    int idx = blockIdx.x * blockDim.x + threadIdx.x;
    if (idx >= ETOT) return;
    int src, p, o;
    decode_edge(idx, triples, src, p, o);
    int pos = atomicAdd(&g_keyoff[src * R2 + p], 1);
    g_sorted[pos] = (p << 16) | o;
}

// ---------------------------------------------------------------------------
// Layer 1: 16-thread group per node, register accumulation, no atomics.
// h[u] = b0 + sum_{edges from u} val * w0[p*N+o]
// ---------------------------------------------------------------------------
__global__ void k_layer1(const float* __restrict__ w0, const float* __restrict__ b0) {
    int t = blockIdx.x * blockDim.x + threadIdx.x;
    int u = t >> 4, lane = t & 15;
    if (u >= N_NODES) return;
    int s = (u == 0) ? 0 : g_keyoff[u * R2 - 1];
    int e = g_keyoff[u * R2 + R2 - 1];

    const float4* w0f4 = reinterpret_cast<const float4*>(w0);
    float4 acc = make_float4(0.f, 0.f, 0.f, 0.f);
    for (int i = s; i < e; i++) {
        int packed = g_sorted[i];
        int p = packed >> 16, o = packed & 0xFFFF;
        int col = p * N_NODES + o;
        float val = 1.0f / (float)g_colsum[col];
        float4 w = __ldg(w0f4 + (size_t)col * 16 + lane);
        acc.x = fmaf(val, w.x, acc.x);
        acc.y = fmaf(val, w.y, acc.y);
        acc.z = fmaf(val, w.z, acc.z);
        acc.w = fmaf(val, w.w, acc.w);
    }
    float4 bb = __ldg(reinterpret_cast<const float4*>(b0) + lane);
    float4 r = make_float4(bb.x + acc.x, bb.y + acc.y, bb.z + acc.z, bb.w + acc.w);
    *reinterpret_cast<float4*>(g_h + u * 64 + lane * 4) = r;
}

// ---------------------------------------------------------------------------
__global__ void k_flag(const int* __restrict__ batch) {
    int b = blockIdx.x * blockDim.x + threadIdx.x;
    if (b < BATCH) {
        g_flag[batch[3 * b + 0]] = 1;
        g_flag[batch[3 * b + 2]] = 1;
    }
}

__global__ void k_compact() {
    int u = blockIdx.x * blockDim.x + threadIdx.x;
    if (u < N_NODES && g_flag[u]) {
        int i = atomicAdd(&g_cnt[0], 1);
        g_list[i] = u;
    }
}

// ---------------------------------------------------------------------------
// Layer 2: one warp per flagged node. Edges are p-sorted within the node,
// so accumulate hsum per p-run in registers, apply w1[p] once per run.
// nodes[u] = b1 + sum_p ( (sum_{(u,p,o)} val*h[o]) @ w1[p] )
// Lane owns output cols {2*lane, 2*lane+1}; hsum staged via shared.
// ---------------------------------------------------------------------------
__global__ void k_layer2(const float* __restrict__ w1, const float* __restrict__ b1) {
    int t = blockIdx.x * blockDim.x + threadIdx.x;
    int w = t >> 5, lane = t & 31;
    int wid = threadIdx.x >> 5;                 // warp in block (8)
    __shared__ float hs[8][64];

    if (w >= N_NODES) return;
    int cnt = g_cnt[0];
    if (w >= cnt) return;
    int u = g_list[w];

    int s = (u == 0) ? 0 : g_keyoff[u * R2 - 1];
    int e = g_keyoff[u * R2 + R2 - 1];

    float2 out  = make_float2(0.f, 0.f);
    float2 hacc = make_float2(0.f, 0.f);
    int curp = -1;

    for (int i = s; i <= e; i++) {
        int p = -2, o = 0;
        if (i < e) {
            int packed = g_sorted[i];
            p = packed >> 16; o = packed & 0xFFFF;
        }
        if (p != curp) {
            if (curp >= 0) {
                // flush run: out += hsum @ w1[curp]
                *reinterpret_cast<float2*>(&hs[wid][2 * lane]) = hacc;
                __syncwarp();
                const float2* W2 = reinterpret_cast<const float2*>(w1 + curp * 4096);
                #pragma unroll
                for (int k4 = 0; k4 < 16; k4++) {
                    float4 h4 = *reinterpret_cast<const float4*>(&hs[wid][k4 * 4]);
                    float2 wv;
                    wv = __ldg(W2 + (k4 * 4 + 0) * 32 + lane);
                    out.x = fmaf(h4.x, wv.x, out.x); out.y = fmaf(h4.x, wv.y, out.y);
                    wv = __ldg(W2 + (k4 * 4 + 1) * 32 + lane);
                    out.x = fmaf(h4.y, wv.x, out.x); out.y = fmaf(h4.y, wv.y, out.y);
                    wv = __ldg(W2 + (k4 * 4 + 2) * 32 + lane);
                    out.x = fmaf(h4.z, wv.x, out.x); out.y = fmaf(h4.z, wv.y, out.y);
                    wv = __ldg(W2 + (k4 * 4 + 3) * 32 + lane);
                    out.x = fmaf(h4.w, wv.x, out.x); out.y = fmaf(h4.w, wv.y, out.y);
                }
                __syncwarp();
            }
            curp = p;
            hacc = make_float2(0.f, 0.f);
        }
        if (i < e) {
            float val = 1.0f / (float)g_colsum[p * N_NODES + o];
            float2 hv = *reinterpret_cast<const float2*>(g_h + o * 64 + 2 * lane);
            hacc.x = fmaf(val, hv.x, hacc.x);
            hacc.y = fmaf(val, hv.y, hacc.y);
        }
    }

    float2 bb = *reinterpret_cast<const float2*>(b1 + 2 * lane);
    float2 r = make_float2(bb.x + out.x, bb.y + out.y);
    *reinterpret_cast<float2*>(g_nodes + u * 64 + 2 * lane) = r;
}

// ---------------------------------------------------------------------------
__global__ void k_score(const int* __restrict__ batch, const float* __restrict__ rel,
                        float* __restrict__ out) {
    int t = blockIdx.x * blockDim.x + threadIdx.x;
    int b = t >> 5, lane = t & 31;
    if (b >= BATCH) return;
    int si = batch[3 * b + 0];
    int pi = batch[3 * b + 1];
    int oi = batch[3 * b + 2];
    const float* ns = g_nodes + si * 64;
    const float* no = g_nodes + oi * 64;
    const float* rr = rel + pi * 64;
    float a = ns[lane]      * rr[lane]      * no[lane]
            + ns[lane + 32] * rr[lane + 32] * no[lane + 32];
    #pragma unroll
    for (int off = 16; off; off >>= 1)
        a += __shfl_xor_sync(0xffffffffu, a, off);
    if (lane == 0) out[b] = a;
}

// ---------------------------------------------------------------------------
extern "C" void kernel_launch(void* const* d_in, const int* in_sizes, int n_in,
                              void* d_out, int out_size) {
    const int*   batch     = (const int*)  d_in[0];
    const int*   triples   = (const int*)  d_in[1];
    const float* w0        = (const float*)d_in[2];
    const float* b0        = (const float*)d_in[3];
    const float* w1        = (const float*)d_in[4];
    const float* b1        = (const float*)d_in[5];
    const float* relations = (const float*)d_in[6];
    float* out = (float*)d_out;

    const int TPB = 256;

    k_init<<<(KEYN + TPB - 1) / TPB, TPB>>>();
    k_hist<<<(ETOT + TPB - 1) / TPB, TPB>>>(triples);
    k_scanA<<<SCAN_NB, 256>>>();
    k_scanB<<<1, 512>>>();
    k_scanC<<<SCAN_NB, 256>>>();
    k_scatter<<<(ETOT + TPB - 1) / TPB, TPB>>>(triples);
    k_layer1<<<(N_NODES * 16 + TPB - 1) / TPB, TPB>>>(w0, b0);
    k_flag<<<(BATCH + TPB - 1) / TPB, TPB>>>(batch);
    k_compact<<<(N_NODES + TPB - 1) / TPB, TPB>>>();
    k_layer2<<<(N_NODES * 32 + TPB - 1) / TPB, TPB>>>(w1, b1);
    k_score<<<(BATCH * 32 + TPB - 1) / TPB, TPB>>>(batch, relations, out);
}